// round 3
// baseline (speedup 1.0000x reference)
#include <cuda_runtime.h>
#include <cuda_bf16.h>
#include <cstdint>

// ---------------------------------------------------------------------------
// DeltaOnlyModel: B=256, L=2048, H=V=64.
// Encoder collapses to 64-entry vocab tables (k normalized, v, q, thr^2) plus
// the 64x64 Gram matrix G[a][b] = k_a . k_b.
// Scan: 1 block / batch element, 64 threads, M row-per-thread in registers.
// 4-step speculative blocking: one reduction + one barrier per 4 tokens;
// next-block preds overlap the exchange and are corrected via Gram.
// ---------------------------------------------------------------------------

#define H 64
#define V 64
#define L 2048
#define B 256

__device__ float g_ktab[V * H];
__device__ float g_vtab[V * H];
__device__ float g_qtab[V * H];
__device__ float g_gram[V * V];
__device__ float g_thr2[V];

typedef unsigned long long ull;

__device__ __forceinline__ ull ffma2(ull a, ull b, ull c) {
    ull d;
    asm("fma.rn.f32x2 %0, %1, %2, %3;" : "=l"(d) : "l"(a), "l"(b), "l"(c));
    return d;
}
__device__ __forceinline__ ull fadd2(ull a, ull b) {
    ull d;
    asm("add.rn.f32x2 %0, %1, %2;" : "=l"(d) : "l"(a), "l"(b));
    return d;
}
__device__ __forceinline__ ull pack2(float lo, float hi) {
    ull d;
    asm("mov.b64 %0, {%1, %2};" : "=l"(d) : "f"(lo), "f"(hi));
    return d;
}
__device__ __forceinline__ void unpack2(ull a, float& lo, float& hi) {
    asm("mov.b64 {%0, %1}, %2;" : "=f"(lo), "=f"(hi) : "l"(a));
}
__device__ __forceinline__ float hsum2(ull a, ull b) {
    float lo, hi;
    unpack2(fadd2(a, b), lo, hi);
    return lo + hi;
}

// ---------------------------------------------------------------------------
// Table builder: one block per vocab entry, 64 threads.
// ---------------------------------------------------------------------------
__global__ void build_tables(const float* __restrict__ embed,
                             const float* __restrict__ w1,
                             const float* __restrict__ b1,
                             const float* __restrict__ w2,
                             const float* __restrict__ b2,
                             const float* __restrict__ ln_g,
                             const float* __restrict__ ln_b,
                             const float* __restrict__ wk,
                             const float* __restrict__ wv,
                             const float* __restrict__ wq) {
    __shared__ float se[H];
    __shared__ float su[2 * H];
    __shared__ float sh[H];
    __shared__ float sred[H];

    const int c = blockIdx.x;
    const int j = threadIdx.x;

    se[j] = embed[c * H + j];
    __syncthreads();

    #pragma unroll
    for (int rep = 0; rep < 2; rep++) {
        const int m = j + rep * H;
        float a = b1[m];
        #pragma unroll 8
        for (int i = 0; i < H; i++) a = fmaf(se[i], w1[i * (2 * H) + m], a);
        su[m] = fmaxf(a, 0.0f);
    }
    __syncthreads();

    float f = b2[j];
    #pragma unroll 8
    for (int m = 0; m < 2 * H; m++) f = fmaf(su[m], w2[m * H + j], f);

    const float s = se[j] + f;
    sh[j] = s;
    __syncthreads();

    float mu = 0.0f;
    #pragma unroll 8
    for (int i = 0; i < H; i++) mu += sh[i];
    mu *= (1.0f / H);
    float var = 0.0f;
    #pragma unroll 8
    for (int i = 0; i < H; i++) { float d = sh[i] - mu; var = fmaf(d, d, var); }
    var *= (1.0f / H);
    const float hn = (s - mu) * rsqrtf(var + 1e-5f) * ln_g[j] + ln_b[j];
    __syncthreads();
    sh[j] = hn;
    __syncthreads();

    float kr = 0.0f;
    #pragma unroll 8
    for (int i = 0; i < H; i++) kr = fmaf(sh[i], wk[i * H + j], kr);
    sred[j] = kr * kr;
    __syncthreads();
    float nk = 0.0f;
    #pragma unroll 8
    for (int i = 0; i < H; i++) nk += sred[i];
    nk = fmaxf(sqrtf(nk), 1e-12f);
    g_ktab[c * H + j] = kr / nk;
    __syncthreads();

    float vr = 0.0f;
    #pragma unroll 8
    for (int i = 0; i < H; i++) vr = fmaf(sh[i], wv[i * H + j], vr);
    g_vtab[c * H + j] = vr;
    sred[j] = vr * vr;
    __syncthreads();
    float nv = 0.0f;
    #pragma unroll 8
    for (int i = 0; i < H; i++) nv += sred[i];
    if (j == 0) g_thr2[c] = 0.16f * nv;

    float qr = 0.0f;
    #pragma unroll 8
    for (int i = 0; i < H; i++) qr = fmaf(sh[i], wq[i * H + j], qr);
    g_qtab[c * H + j] = qr;
}

// Gram matrix of normalized keys: G[a][b] = k_a . k_b
__global__ void gram_kernel() {
    __shared__ float ka[H];
    const int a = blockIdx.x;
    const int j = threadIdx.x;
    ka[j] = g_ktab[a * H + j];
    __syncthreads();
    float s = 0.0f;
    #pragma unroll 8
    for (int i = 0; i < H; i++) s = fmaf(ka[i], g_ktab[j * H + i], s);
    g_gram[a * H + j] = s;
}

// ---------------------------------------------------------------------------
// Scan: 4-step speculative blocks.
// ---------------------------------------------------------------------------
__global__ __launch_bounds__(64) void scan_kernel(const int* __restrict__ x,
                                                  const float* __restrict__ wo,
                                                  const float* __restrict__ bo,
                                                  float* __restrict__ out) {
    __shared__ __align__(16) float sk[V * H];   // 16 KB normalized k
    __shared__ float sG[V * V];                 // 16 KB Gram
    __shared__ int   sx[L];                     // 8 KB tokens
    __shared__ float sthr[V];
    __shared__ ull   sxch[2][2][5];             // [parity][warp][packed dots]
    __shared__ float sfin[H];

    const int b    = blockIdx.x;
    const int tid  = threadIdx.x;
    const int lane = tid & 31;
    const int w    = tid >> 5;

    for (int i = tid; i < V * H; i += 64) {
        sk[i] = g_ktab[i];
        sG[i] = g_gram[i];
    }
    sthr[tid] = g_thr2[tid];
    const int* xb = x + b * L;
    for (int i = tid; i < L; i += 64) sx[i] = xb[i];
    __syncthreads();

    ull m2[32];
    #pragma unroll
    for (int i = 0; i < 32; i++) m2[i] = 0ULL;

    int tk0 = sx[0], tk1 = sx[1], tk2 = sx[2], tk3 = sx[3];
    float vv0 = g_vtab[(tk0 << 6) + tid];
    float vv1 = g_vtab[(tk1 << 6) + tid];
    float vv2 = g_vtab[(tk2 << 6) + tid];
    float vv3 = g_vtab[(tk3 << 6) + tid];
    float P0 = 0.0f, P1 = 0.0f, P2 = 0.0f, P3 = 0.0f;

    for (int t = 0; t < L; t += 4) {
        const int nt = (t + 4) & (L - 1);
        const int nk0 = sx[nt], nk1 = sx[nt + 1], nk2 = sx[nt + 2], nk3 = sx[nt + 3];
        // prefetch next v (L2-resident, consumed next iteration)
        const float nv0 = g_vtab[(nk0 << 6) + tid];
        const float nv1 = g_vtab[(nk1 << 6) + tid];
        const float nv2 = g_vtab[(nk2 << 6) + tid];
        const float nv3 = g_vtab[(nk3 << 6) + tid];

        const float th0 = sthr[tk0], th1 = sthr[tk1], th2 = sthr[tk2], th3 = sthr[tk3];
        const float G01 = sG[(tk0 << 6) + tk1];
        const float G02 = sG[(tk0 << 6) + tk2];
        const float G03 = sG[(tk0 << 6) + tk3];
        const float G12 = sG[(tk1 << 6) + tk2];
        const float G13 = sG[(tk1 << 6) + tk3];
        const float G23 = sG[(tk2 << 6) + tk3];

        // residuals vs block-entry M
        const float vt0 = vv0 - P0;
        const float vt1 = vv1 - P1;
        const float vt2 = vv2 - P2;
        const float vt3 = vv3 - P3;

        // 10 dot-product partials packed as 5 f32x2
        ull u0 = pack2(vt0 * vt0, vt0 * vt1);
        ull u1 = pack2(vt0 * vt2, vt0 * vt3);
        ull u2 = pack2(vt1 * vt1, vt1 * vt2);
        ull u3 = pack2(vt1 * vt3, vt2 * vt2);
        ull u4 = pack2(vt2 * vt3, vt3 * vt3);
        #pragma unroll
        for (int st = 16; st; st >>= 1) {
            u0 = fadd2(u0, __shfl_xor_sync(0xffffffffu, u0, st));
            u1 = fadd2(u1, __shfl_xor_sync(0xffffffffu, u1, st));
            u2 = fadd2(u2, __shfl_xor_sync(0xffffffffu, u2, st));
            u3 = fadd2(u3, __shfl_xor_sync(0xffffffffu, u3, st));
            u4 = fadd2(u4, __shfl_xor_sync(0xffffffffu, u4, st));
        }
        const int pb = (t >> 2) & 1;
        if (lane == 0) {
            sxch[pb][w][0] = u0; sxch[pb][w][1] = u1; sxch[pb][w][2] = u2;
            sxch[pb][w][3] = u3; sxch[pb][w][4] = u4;
        }

        // next-block preds against pre-update M (overlaps the exchange)
        const ulonglong2* kn0 = reinterpret_cast<const ulonglong2*>(sk + (nk0 << 6));
        const ulonglong2* kn1 = reinterpret_cast<const ulonglong2*>(sk + (nk1 << 6));
        const ulonglong2* kn2 = reinterpret_cast<const ulonglong2*>(sk + (nk2 << 6));
        const ulonglong2* kn3 = reinterpret_cast<const ulonglong2*>(sk + (nk3 << 6));
        ull a00 = 0, a01 = 0, a10 = 0, a11 = 0, a20 = 0, a21 = 0, a30 = 0, a31 = 0;
        #pragma unroll
        for (int q = 0; q < 16; q++) {
            const ulonglong2 kk0 = kn0[q];
            const ulonglong2 kk1 = kn1[q];
            const ulonglong2 kk2 = kn2[q];
            const ulonglong2 kk3 = kn3[q];
            a00 = ffma2(m2[2 * q], kk0.x, a00); a01 = ffma2(m2[2 * q + 1], kk0.y, a01);
            a10 = ffma2(m2[2 * q], kk1.x, a10); a11 = ffma2(m2[2 * q + 1], kk1.y, a11);
            a20 = ffma2(m2[2 * q], kk2.x, a20); a21 = ffma2(m2[2 * q + 1], kk2.y, a21);
            a30 = ffma2(m2[2 * q], kk3.x, a30); a31 = ffma2(m2[2 * q + 1], kk3.y, a31);
        }

        __syncthreads();
        const ull f0 = fadd2(sxch[pb][0][0], sxch[pb][1][0]);
        const ull f1 = fadd2(sxch[pb][0][1], sxch[pb][1][1]);
        const ull f2 = fadd2(sxch[pb][0][2], sxch[pb][1][2]);
        const ull f3 = fadd2(sxch[pb][0][3], sxch[pb][1][3]);
        const ull f4 = fadd2(sxch[pb][0][4], sxch[pb][1][4]);
        float S00, S01, S02, S03, S11, S12, S13, S22, S23, S33;
        unpack2(f0, S00, S01);
        unpack2(f1, S02, S03);
        unpack2(f2, S11, S12);
        unpack2(f3, S13, S22);
        unpack2(f4, S23, S33);

        // scalar gate chain (redundant on all threads, bitwise identical)
        const bool g0 = S00 > th0;
        const float w10 = g0 ? -G01 : 0.0f;
        const float n1s = S11 + w10 * (2.0f * S01 + w10 * S00);
        const bool g1 = n1s > th1;
        const float w21 = g1 ? -G12 : 0.0f;
        const float w20 = (g0 ? -G02 : 0.0f) + w21 * w10;
        const float n2s = S22 + w20 * (w20 * S00 + 2.0f * S02)
                              + w21 * (w21 * S11 + 2.0f * S12)
                              + 2.0f * w20 * w21 * S01;
        const bool g2 = n2s > th2;
        const float w32 = g2 ? -G23 : 0.0f;
        const float t13 = g1 ? -G13 : 0.0f;
        const float w31 = t13 + w32 * w21;
        const float w30 = (g0 ? -G03 : 0.0f) + t13 * w10 + w32 * w20;
        const float n3s = S33 + w30 * (w30 * S00 + 2.0f * S03)
                              + w31 * (w31 * S11 + 2.0f * S13)
                              + w32 * (w32 * S22 + 2.0f * S23)
                              + 2.0f * (w30 * w31 * S01 + w30 * w32 * S02 + w31 * w32 * S12);
        const bool g3 = n3s > th3;

        // per-thread delta components
        const float d0 = vt0;
        const float d1 = vt1 + w10 * vt0;
        const float d2 = vt2 + w20 * vt0 + w21 * vt1;
        const float d3 = vt3 + w30 * vt0 + w31 * vt1 + w32 * vt2;

        float Pn0 = hsum2(a00, a01);
        float Pn1 = hsum2(a10, a11);
        float Pn2 = hsum2(a20, a21);
        float Pn3 = hsum2(a30, a31);

        // gated rank-1 updates + exact Gram correction of next preds
        if (g0) {
            const ull dd = pack2(d0, d0);
            const ulonglong2* kp = reinterpret_cast<const ulonglong2*>(sk + (tk0 << 6));
            #pragma unroll
            for (int q = 0; q < 16; q++) {
                const ulonglong2 kk = kp[q];
                m2[2 * q]     = ffma2(dd, kk.x, m2[2 * q]);
                m2[2 * q + 1] = ffma2(dd, kk.y, m2[2 * q + 1]);
            }
            Pn0 = fmaf(d0, sG[(tk0 << 6) + nk0], Pn0);
            Pn1 = fmaf(d0, sG[(tk0 << 6) + nk1], Pn1);
            Pn2 = fmaf(d0, sG[(tk0 << 6) + nk2], Pn2);
            Pn3 = fmaf(d0, sG[(tk0 << 6) + nk3], Pn3);
        }
        if (g1) {
            const ull dd = pack2(d1, d1);
            const ulonglong2* kp = reinterpret_cast<const ulonglong2*>(sk + (tk1 << 6));
            #pragma unroll
            for (int q = 0; q < 16; q++) {
                const ulonglong2 kk = kp[q];
                m2[2 * q]     = ffma2(dd, kk.x, m2[2 * q]);
                m2[2 * q + 1] = ffma2(dd, kk.y, m2[2 * q + 1]);
            }
            Pn0 = fmaf(d1, sG[(tk1 << 6) + nk0], Pn0);
            Pn1 = fmaf(d1, sG[(tk1 << 6) + nk1], Pn1);
            Pn2 = fmaf(d1, sG[(tk1 << 6) + nk2], Pn2);
            Pn3 = fmaf(d1, sG[(tk1 << 6) + nk3], Pn3);
        }
        if (g2) {
            const ull dd = pack2(d2, d2);
            const ulonglong2* kp = reinterpret_cast<const ulonglong2*>(sk + (tk2 << 6));
            #pragma unroll
            for (int q = 0; q < 16; q++) {
                const ulonglong2 kk = kp[q];
                m2[2 * q]     = ffma2(dd, kk.x, m2[2 * q]);
                m2[2 * q + 1] = ffma2(dd, kk.y, m2[2 * q + 1]);
            }
            Pn0 = fmaf(d2, sG[(tk2 << 6) + nk0], Pn0);
            Pn1 = fmaf(d2, sG[(tk2 << 6) + nk1], Pn1);
            Pn2 = fmaf(d2, sG[(tk2 << 6) + nk2], Pn2);
            Pn3 = fmaf(d2, sG[(tk2 << 6) + nk3], Pn3);
        }
        if (g3) {
            const ull dd = pack2(d3, d3);
            const ulonglong2* kp = reinterpret_cast<const ulonglong2*>(sk + (tk3 << 6));
            #pragma unroll
            for (int q = 0; q < 16; q++) {
                const ulonglong2 kk = kp[q];
                m2[2 * q]     = ffma2(dd, kk.x, m2[2 * q]);
                m2[2 * q + 1] = ffma2(dd, kk.y, m2[2 * q + 1]);
            }
            Pn0 = fmaf(d3, sG[(tk3 << 6) + nk0], Pn0);
            Pn1 = fmaf(d3, sG[(tk3 << 6) + nk1], Pn1);
            Pn2 = fmaf(d3, sG[(tk3 << 6) + nk2], Pn2);
            Pn3 = fmaf(d3, sG[(tk3 << 6) + nk3], Pn3);
        }

        P0 = Pn0; P1 = Pn1; P2 = Pn2; P3 = Pn3;
        tk0 = nk0; tk1 = nk1; tk2 = nk2; tk3 = nk3;
        vv0 = nv0; vv1 = nv1; vv2 = nv2; vv3 = nv3;
    }

    // Readout: q = q_tab[last token]; read = relu(M q); out = read @ wo + bo
    const int tokL = sx[L - 1];
    const float* qv = g_qtab + (tokL << 6);
    float r = 0.0f;
    #pragma unroll
    for (int j = 0; j < 32; j++) {
        float lo, hi;
        unpack2(m2[j], lo, hi);
        r = fmaf(lo, qv[2 * j], r);
        r = fmaf(hi, qv[2 * j + 1], r);
    }
    r = fmaxf(r, 0.0f);
    sfin[tid] = r;
    __syncthreads();

    float oacc = bo[tid];
    #pragma unroll 8
    for (int i = 0; i < H; i++) oacc = fmaf(sfin[i], wo[(i << 6) + tid], oacc);
    out[(b << 6) + tid] = oacc;
}

// ---------------------------------------------------------------------------
// Inputs: x, embed, w1, b1, w2, b2, ln_g, ln_b, wk, wv, wq, wo, bo
// ---------------------------------------------------------------------------
extern "C" void kernel_launch(void* const* d_in, const int* in_sizes, int n_in,
                              void* d_out, int out_size) {
    const int*   x     = (const int*)d_in[0];
    const float* embed = (const float*)d_in[1];
    const float* w1    = (const float*)d_in[2];
    const float* b1    = (const float*)d_in[3];
    const float* w2    = (const float*)d_in[4];
    const float* b2    = (const float*)d_in[5];
    const float* ln_g  = (const float*)d_in[6];
    const float* ln_b  = (const float*)d_in[7];
    const float* wk    = (const float*)d_in[8];
    const float* wv    = (const float*)d_in[9];
    const float* wq    = (const float*)d_in[10];
    const float* wo    = (const float*)d_in[11];
    const float* bo    = (const float*)d_in[12];
    float*       out   = (float*)d_out;

    build_tables<<<V, H>>>(embed, w1, b1, w2, b2, ln_g, ln_b, wk, wv, wq);
    gram_kernel<<<V, H>>>();
    scan_kernel<<<B, H>>>(x, wo, bo, out);
}

// round 5
// speedup vs baseline: 1.0514x; 1.0514x over previous
#include <cuda_runtime.h>
#include <cuda_bf16.h>
#include <cstdint>

// ---------------------------------------------------------------------------
// DeltaOnlyModel: B=256, L=2048, H=V=64.
// Encoder collapses to 64-entry vocab tables (k normalized, v, q, thr^2) plus
// the 64x64 key Gram matrix. Scan: 1 block/batch, 64 threads, M row/thread in
// registers. Per step: shfl-butterfly + smem exchange for the gate norm, with
// the NEXT step's pred speculatively issued (vs pre-update M) inside the
// exchange window and corrected exactly via one Gram FMA. Branchless gate.
// ---------------------------------------------------------------------------

#define H 64
#define V 64
#define L 2048
#define B 256

__device__ float g_ktab[V * H];
__device__ float g_vtab[V * H];
__device__ float g_qtab[V * H];
__device__ float g_gram[V * V];
__device__ float g_thr2[V];

typedef unsigned long long ull;

__device__ __forceinline__ ull ffma2(ull a, ull b, ull c) {
    ull d;
    asm("fma.rn.f32x2 %0, %1, %2, %3;" : "=l"(d) : "l"(a), "l"(b), "l"(c));
    return d;
}
__device__ __forceinline__ ull fadd2(ull a, ull b) {
    ull d;
    asm("add.rn.f32x2 %0, %1, %2;" : "=l"(d) : "l"(a), "l"(b));
    return d;
}
__device__ __forceinline__ ull pack2(float lo, float hi) {
    ull d;
    asm("mov.b64 %0, {%1, %2};" : "=l"(d) : "f"(lo), "f"(hi));
    return d;
}
__device__ __forceinline__ void unpack2(ull a, float& lo, float& hi) {
    asm("mov.b64 {%0, %1}, %2;" : "=f"(lo), "=f"(hi) : "l"(a));
}

// ---------------------------------------------------------------------------
// Table builder: one block per vocab entry, 64 threads.
// ---------------------------------------------------------------------------
__global__ void build_tables(const float* __restrict__ embed,
                             const float* __restrict__ w1,
                             const float* __restrict__ b1,
                             const float* __restrict__ w2,
                             const float* __restrict__ b2,
                             const float* __restrict__ ln_g,
                             const float* __restrict__ ln_b,
                             const float* __restrict__ wk,
                             const float* __restrict__ wv,
                             const float* __restrict__ wq) {
    __shared__ float se[H];
    __shared__ float su[2 * H];
    __shared__ float sh[H];
    __shared__ float sred[H];

    const int c = blockIdx.x;
    const int j = threadIdx.x;

    se[j] = embed[c * H + j];
    __syncthreads();

    #pragma unroll
    for (int rep = 0; rep < 2; rep++) {
        const int m = j + rep * H;
        float a = b1[m];
        #pragma unroll 8
        for (int i = 0; i < H; i++) a = fmaf(se[i], w1[i * (2 * H) + m], a);
        su[m] = fmaxf(a, 0.0f);
    }
    __syncthreads();

    float f = b2[j];
    #pragma unroll 8
    for (int m = 0; m < 2 * H; m++) f = fmaf(su[m], w2[m * H + j], f);

    const float s = se[j] + f;
    sh[j] = s;
    __syncthreads();

    float mu = 0.0f;
    #pragma unroll 8
    for (int i = 0; i < H; i++) mu += sh[i];
    mu *= (1.0f / H);
    float var = 0.0f;
    #pragma unroll 8
    for (int i = 0; i < H; i++) { float d = sh[i] - mu; var = fmaf(d, d, var); }
    var *= (1.0f / H);
    const float hn = (s - mu) * rsqrtf(var + 1e-5f) * ln_g[j] + ln_b[j];
    __syncthreads();
    sh[j] = hn;
    __syncthreads();

    float kr = 0.0f;
    #pragma unroll 8
    for (int i = 0; i < H; i++) kr = fmaf(sh[i], wk[i * H + j], kr);
    sred[j] = kr * kr;
    __syncthreads();
    float nk = 0.0f;
    #pragma unroll 8
    for (int i = 0; i < H; i++) nk += sred[i];
    nk = fmaxf(sqrtf(nk), 1e-12f);
    g_ktab[c * H + j] = kr / nk;
    __syncthreads();

    float vr = 0.0f;
    #pragma unroll 8
    for (int i = 0; i < H; i++) vr = fmaf(sh[i], wv[i * H + j], vr);
    g_vtab[c * H + j] = vr;
    sred[j] = vr * vr;
    __syncthreads();
    float nv = 0.0f;
    #pragma unroll 8
    for (int i = 0; i < H; i++) nv += sred[i];
    if (j == 0) g_thr2[c] = 0.16f * nv;

    float qr = 0.0f;
    #pragma unroll 8
    for (int i = 0; i < H; i++) qr = fmaf(sh[i], wq[i * H + j], qr);
    g_qtab[c * H + j] = qr;
}

// Gram matrix of normalized keys: G[a][b] = k_a . k_b
__global__ void gram_kernel() {
    __shared__ float ka[H];
    const int a = blockIdx.x;
    const int j = threadIdx.x;
    ka[j] = g_ktab[a * H + j];
    __syncthreads();
    float s = 0.0f;
    #pragma unroll 8
    for (int i = 0; i < H; i++) s = fmaf(ka[i], g_ktab[j * H + i], s);
    g_gram[a * H + j] = s;
}

// ---------------------------------------------------------------------------
// Scan kernel.
// ---------------------------------------------------------------------------
__global__ __launch_bounds__(64) void scan_kernel(const int* __restrict__ x,
                                                  const float* __restrict__ wo,
                                                  const float* __restrict__ bo,
                                                  float* __restrict__ out) {
    __shared__ __align__(16) float sk[V * H];   // 16 KB normalized k
    __shared__ float sv[V * H];                 // 16 KB v table
    __shared__ float sG[V * V];                 // 16 KB Gram
    __shared__ float sthr[V];
    __shared__ int   sx[L];                     // 8 KB tokens
    __shared__ float sxch[2][2];                // [parity][warp]
    __shared__ float sfin[H];

    const int b    = blockIdx.x;
    const int tid  = threadIdx.x;
    const int lane = tid & 31;
    const int w    = tid >> 5;

    for (int i = tid; i < V * H; i += 64) {
        sk[i] = g_ktab[i];
        sv[i] = g_vtab[i];
        sG[i] = g_gram[i];
    }
    sthr[tid] = g_thr2[tid];
    const int* xb = x + b * L;
    for (int i = tid; i < L; i += 64) sx[i] = xb[i];
    __syncthreads();

    ull m2[32];
    #pragma unroll
    for (int i = 0; i < 32; i++) m2[i] = 0ULL;

    int   tok  = sx[0];
    float vcur = sv[(tok << 6) + tid];
    float P    = 0.0f;   // exact pred for current step

    for (int t = 0; t < L; t++) {
        // gate statistic for this step: ||delta||^2 over 64 threads
        const float delta = vcur - P;
        float ws = delta * delta;
        #pragma unroll
        for (int o = 16; o > 0; o >>= 1)
            ws += __shfl_xor_sync(0xffffffffu, ws, o);
        const int pb = t & 1;
        if (lane == 0) sxch[pb][w] = ws;

        // next token / value (independent of the exchange)
        const int tokn = sx[(t + 1) & (L - 1)];
        const float vn = sv[(tokn << 6) + tid];
        const float thr = sthr[tok];

        // speculative pred for next step against PRE-update M
        // (issued inside the butterfly/exchange stall window)
        const ulonglong2* kn = reinterpret_cast<const ulonglong2*>(sk + (tokn << 6));
        ull a0 = 0, a1 = 0, a2 = 0, a3 = 0;
        #pragma unroll
        for (int j = 0; j < 8; j++) {
            const ulonglong2 kA = kn[2 * j];
            const ulonglong2 kB = kn[2 * j + 1];
            a0 = ffma2(m2[4 * j + 0], kA.x, a0);
            a1 = ffma2(m2[4 * j + 1], kA.y, a1);
            a2 = ffma2(m2[4 * j + 2], kB.x, a2);
            a3 = ffma2(m2[4 * j + 3], kB.y, a3);
        }

        __syncthreads();
        const float tot = sxch[pb][0] + sxch[pb][1];

        // branchless gate
        const float du = (tot > thr) ? delta : 0.0f;

        // rank-1 update with current token's k (broadcast smem loads)
        const ull dd = pack2(du, du);
        const ulonglong2* kc = reinterpret_cast<const ulonglong2*>(sk + (tok << 6));
        #pragma unroll
        for (int j = 0; j < 8; j++) {
            const ulonglong2 kA = kc[2 * j];
            const ulonglong2 kB = kc[2 * j + 1];
            m2[4 * j + 0] = ffma2(dd, kA.x, m2[4 * j + 0]);
            m2[4 * j + 1] = ffma2(dd, kA.y, m2[4 * j + 1]);
            m2[4 * j + 2] = ffma2(dd, kB.x, m2[4 * j + 2]);
            m2[4 * j + 3] = ffma2(dd, kB.y, m2[4 * j + 3]);
        }

        // finalize next pred: horizontal sum + exact Gram correction
        float plo, phi;
        unpack2(fadd2(fadd2(a0, a1), fadd2(a2, a3)), plo, phi);
        P = fmaf(du, sG[(tok << 6) + tokn], plo + phi);

        tok  = tokn;
        vcur = vn;
    }

    // Readout: q = q_tab[last token]; read = relu(M q); out = read @ wo + bo
    const int tokL = sx[L - 1];
    const float* qv = g_qtab + (tokL << 6);
    float r = 0.0f;
    #pragma unroll
    for (int j = 0; j < 32; j++) {
        float lo, hi;
        unpack2(m2[j], lo, hi);
        r = fmaf(lo, qv[2 * j], r);
        r = fmaf(hi, qv[2 * j + 1], r);
    }
    r = fmaxf(r, 0.0f);
    sfin[tid] = r;
    __syncthreads();

    float oacc = bo[tid];
    #pragma unroll 8
    for (int i = 0; i < H; i++) oacc = fmaf(sfin[i], wo[(i << 6) + tid], oacc);
    out[(b << 6) + tid] = oacc;
}

// ---------------------------------------------------------------------------
// Inputs: x, embed, w1, b1, w2, b2, ln_g, ln_b, wk, wv, wq, wo, bo
// ---------------------------------------------------------------------------
extern "C" void kernel_launch(void* const* d_in, const int* in_sizes, int n_in,
                              void* d_out, int out_size) {
    const int*   x     = (const int*)d_in[0];
    const float* embed = (const float*)d_in[1];
    const float* w1    = (const float*)d_in[2];
    const float* b1    = (const float*)d_in[3];
    const float* w2    = (const float*)d_in[4];
    const float* b2    = (const float*)d_in[5];
    const float* ln_g  = (const float*)d_in[6];
    const float* ln_b  = (const float*)d_in[7];
    const float* wk    = (const float*)d_in[8];
    const float* wv    = (const float*)d_in[9];
    const float* wq    = (const float*)d_in[10];
    const float* wo    = (const float*)d_in[11];
    const float* bo    = (const float*)d_in[12];
    float*       out   = (float*)d_out;

    build_tables<<<V, H>>>(embed, w1, b1, w2, b2, ln_g, ln_b, wk, wv, wq);
    gram_kernel<<<V, H>>>();
    scan_kernel<<<B, H>>>(x, wo, bo, out);
}